// round 9
// baseline (speedup 1.0000x reference)
#include <cuda_runtime.h>
#include <cuda_bf16.h>
#include <math.h>
#include <stdint.h>

#define MAXN 100000
#define D 64
#define K_PAD 208
#define C_TOT 256      // cols: [0:64) r, [64:128) i, [128:192) i_n, [192:256) h_n
#define TILE_N 64      // nodes per tile
#define NTHREADS 1024
#define GRID_SM 148
#define XSTR 68        // Xs row stride in floats (64 nodes + 4 pad; 272B, 16B-multiple)

// smem partition (floats):
//  Mg [194][128] : 24832   gate cols 0-127, K rows 0-193
//  Mi [130][64]  : 8320    i_n cols 128-191, rows 0-127 then 192,193
//  Mh [64][64]   : 4096    h_n cols 192-255, rows 128-191
//  UB [16384]    : union — Xs[194][68] mainloop, Epi[64][256] epilogue
#define OFF_MG 0
#define OFF_MI 24832
#define OFF_MH 33152
#define OFF_UB 37248
#define SMEM_FLOATS 53632   // 214,528 bytes

// ---------------- scratch ----------------
__device__ float g_S[2 * (size_t)MAXN * D];
__device__ float g_s[2 * MAXN];
__device__ float g_M[K_PAD * C_TOT];
__device__ float g_bias[C_TOT];

// ---------------- kernel 1: precompute fused matrix ----------------
__global__ void precompute_kernel(const float* __restrict__ W_in, const float* __restrict__ b_in,
                                  const float* __restrict__ W_out, const float* __restrict__ b_out,
                                  const float* __restrict__ W_ih, const float* __restrict__ b_ih,
                                  const float* __restrict__ W_hh, const float* __restrict__ b_hh) {
    int k = blockIdx.x;
    int c = threadIdx.x;
    float v = 0.f;
    if (k < 64) {
        if (c < 192) {
            float a = 0.f;
            #pragma unroll 8
            for (int t = 0; t < 64; t++) a += W_in[k * 64 + t] * W_ih[t * 192 + c];
            v = a;
        }
    } else if (k < 128) {
        if (c < 192) {
            int aa = k - 64;
            float a = 0.f;
            #pragma unroll 8
            for (int t = 0; t < 64; t++) a += W_out[aa * 64 + t] * W_ih[(64 + t) * 192 + c];
            v = a;
        }
    } else if (k < 192) {
        int aa = k - 128;
        if (c < 128) v = W_hh[aa * 192 + c];
        else if (c >= 192) v = W_hh[aa * 192 + 128 + (c - 192)];
    } else if (k == 192) {
        if (c < 192) {
            float a = 0.f;
            for (int t = 0; t < 64; t++) a += b_in[t] * W_ih[t * 192 + c];
            v = a;
        }
    } else if (k == 193) {
        if (c < 192) {
            float a = 0.f;
            for (int t = 0; t < 64; t++) a += b_out[t] * W_ih[(64 + t) * 192 + c];
            v = a;
        }
    }
    g_M[k * C_TOT + c] = v;
    if (k == 0) {
        float b;
        if (c < 128)      b = b_ih[c] + b_hh[c];
        else if (c < 192) b = b_ih[c];
        else              b = b_hh[c - 64];
        g_bias[c] = b;
    }
}

// ---------------- kernel 2: zero accumulators ----------------
__global__ void zero_kernel(int n) {
    long totS = 2L * n * D;
    long tots = 2L * n;
    long tid = (long)blockIdx.x * blockDim.x + threadIdx.x;
    long stride = (long)gridDim.x * blockDim.x;
    float4 z = make_float4(0.f, 0.f, 0.f, 0.f);
    float4* S4 = reinterpret_cast<float4*>(g_S);
    for (long i = tid; i < totS / 4; i += stride) S4[i] = z;
    long rem = tots / 4;
    float4* s4 = reinterpret_cast<float4*>(g_s);
    for (long i = tid; i < rem; i += stride) s4[i] = z;
    for (long i = rem * 4 + tid; i < tots; i += stride) g_s[i] = 0.f;
}

// ---------------- kernel 3: edge scatter ----------------
__global__ void scatter_kernel(const float4* __restrict__ h4,
                               const int* __restrict__ srcA, const int* __restrict__ dstA,
                               const float* __restrict__ wA,
                               const int* __restrict__ srcB, const int* __restrict__ dstB,
                               const float* __restrict__ wB,
                               int E, int n) {
    int set = blockIdx.y;
    const int*   src = set ? srcB : srcA;
    const int*   dst = set ? dstB : dstA;
    const float* wp  = set ? wB   : wA;
    float* S  = g_S + (size_t)set * n * D;
    float* sw = g_s + (size_t)set * n;

    int lane = threadIdx.x & 31;
    int wid  = (blockIdx.x * blockDim.x + threadIdx.x) >> 5;
    int nw   = (gridDim.x * blockDim.x) >> 5;

    for (long base = (long)wid * 32; base < E; base += (long)nw * 32) {
        long e = base + lane;
        int s = 0, d = 0; float w = 0.f;
        if (e < E) { s = src[e]; d = dst[e]; w = wp[e]; }
        int cnt = (int)min((long)32, (long)E - base);
        for (int j = 0; j < cnt; j += 2) {
            int jj = j + (lane >> 4);
            float ww = __shfl_sync(0xffffffffu, w, jj);
            int   ss = __shfl_sync(0xffffffffu, s, jj);
            int   dd = __shfl_sync(0xffffffffu, d, jj);
            if (jj < cnt) {
                int l = lane & 15;
                float4 v = h4[(size_t)ss * 16 + l];
                float* p = S + (size_t)dd * D + l * 4;
                asm volatile("red.global.add.v4.f32 [%0], {%1,%2,%3,%4};"
                             :: "l"(p), "f"(v.x * ww), "f"(v.y * ww),
                                "f"(v.z * ww), "f"(v.w * ww) : "memory");
                if (l == 0)
                    asm volatile("red.global.add.f32 [%0], %1;"
                                 :: "l"(sw + dd), "f"(ww) : "memory");
            }
        }
    }
}

// ---------------- f32x2 helpers ----------------
typedef unsigned long long u64t;

__device__ __forceinline__ u64t pk2(float v) {
    u64t r;
    asm("mov.b64 %0, {%1, %1};" : "=l"(r) : "f"(v));
    return r;
}
__device__ __forceinline__ u64t fma2(u64t a, u64t b, u64t c) {
    u64t d;
    asm("fma.rn.f32x2 %0, %1, %2, %3;" : "=l"(d) : "l"(a), "l"(b), "l"(c));
    return d;
}
__device__ __forceinline__ void upk2(u64t v, float& lo, float& hi) {
    asm("mov.b64 {%0, %1}, %2;" : "=f"(lo), "=f"(hi) : "l"(v));
}

__device__ __forceinline__ float fsig(float x) { return 1.f / (1.f + __expf(-x)); }
__device__ __forceinline__ float ftanh(float x) { return 2.f / (1.f + __expf(-2.f * x)) - 1.f; }

// one k-step: 8 FMA2 covering 8 nodes x 2 cols
__device__ __forceinline__ void step2(u64t acc[8], const float* mp, const float* xp) {
    float2 m = *reinterpret_cast<const float2*>(mp);
    u64t m0 = pk2(m.x), m1 = pk2(m.y);
    ulonglong2 xa = *reinterpret_cast<const ulonglong2*>(xp);       // nodes 0-3 (2 pairs)
    ulonglong2 xb = *reinterpret_cast<const ulonglong2*>(xp + 4);   // nodes 4-7
    acc[0] = fma2(xa.x, m0, acc[0]); acc[1] = fma2(xa.x, m1, acc[1]);
    acc[2] = fma2(xa.y, m0, acc[2]); acc[3] = fma2(xa.y, m1, acc[3]);
    acc[4] = fma2(xb.x, m0, acc[4]); acc[5] = fma2(xb.x, m1, acc[5]);
    acc[6] = fma2(xb.y, m0, acc[6]); acc[7] = fma2(xb.y, m1, acc[7]);
}

// ---------------- kernel 4: persistent fused node GEMM + GRU (f32x2) ----------------
// 148 CTAs x 1024 threads. Thread tile: 2 cols x 8 nodes.
// Warps 0-15: gates (cols 0-127, K=194): ng=w&7, col-half=w>>3, colb=half*64+lane*2
// Warps 16-23: i_n  (cols 128-191, K=130): ng=w-16, colb=128+lane*2
// Warps 24-31: h_n  (cols 192-255, K=64):  ng=w-24, colb=192+lane*2
// Per-SMSP K-steps: 4*194 + 2*130 + 2*64 = 1164 (balanced).
extern __shared__ float smem[];

__global__ __launch_bounds__(NTHREADS, 1) void node_kernel(const float* __restrict__ hidden,
                                                           float* __restrict__ out,
                                                           int n_nodes, int ntiles) {
    float* Mg = smem + OFF_MG;
    float* Mi = smem + OFF_MI;
    float* Mh = smem + OFF_MH;
    float* UB = smem + OFF_UB;

    int tid = threadIdx.x;
    int wid = tid >> 5;
    int lane = tid & 31;

    // ---- load M panels once ----
    {
        float4* Mg4 = reinterpret_cast<float4*>(Mg);
        for (int i = tid; i < 194 * 32; i += NTHREADS) {
            int r = i >> 5, c4 = i & 31;
            Mg4[i] = *reinterpret_cast<const float4*>(&g_M[r * C_TOT + c4 * 4]);
        }
        float4* Mi4 = reinterpret_cast<float4*>(Mi);
        for (int i = tid; i < 130 * 16; i += NTHREADS) {
            int r = i >> 4, c4 = i & 15;
            int gr = (r < 128) ? r : (192 + (r - 128));
            Mi4[i] = *reinterpret_cast<const float4*>(&g_M[gr * C_TOT + 128 + c4 * 4]);
        }
        float4* Mh4 = reinterpret_cast<float4*>(Mh);
        for (int i = tid; i < 64 * 16; i += NTHREADS) {
            int r = i >> 4, c4 = i & 15;
            Mh4[i] = *reinterpret_cast<const float4*>(&g_M[(128 + r) * C_TOT + 192 + c4 * 4]);
        }
    }
    __syncthreads();

    const float* Sin  = g_S;
    const float* Sout = g_S + (size_t)n_nodes * D;

    // fixed thread -> (colb, ng)
    int colb, ng;
    if (wid < 16)      { ng = wid & 7;  colb = (wid >> 3) * 64 + lane * 2; }
    else if (wid < 24) { ng = wid - 16; colb = 128 + lane * 2; }
    else               { ng = wid - 24; colb = 192 + lane * 2; }

    for (int tile = blockIdx.x; tile < ntiles; tile += gridDim.x) {
        int node0 = tile * TILE_N;

        // ---- build X tile: Xs[k][node], 16 threads per node ----
        {
            int g = tid >> 4;
            int l = tid & 15;
            int n = node0 + g;
            bool nv = (n < n_nodes);
            #pragma unroll
            for (int k = l; k < 194; k += 16) {
                float v = 0.f;
                if (nv) {
                    if (k < 64)        v = Sin[(size_t)n * D + k];
                    else if (k < 128)  v = Sout[(size_t)n * D + (k - 64)];
                    else if (k < 192)  v = hidden[(size_t)n * D + (k - 128)];
                    else if (k == 192) v = g_s[n];
                    else               v = g_s[n_nodes + n];
                }
                UB[k * XSTR + g] = v;
            }
        }
        __syncthreads();

        // ---- barrier-free GEMM, f32x2 ----
        u64t acc[8];
        {
            float2 bv = *reinterpret_cast<const float2*>(&g_bias[colb]);
            u64t b0 = pk2(bv.x), b1 = pk2(bv.y);
            acc[0] = b0; acc[1] = b1; acc[2] = b0; acc[3] = b1;
            acc[4] = b0; acc[5] = b1; acc[6] = b0; acc[7] = b1;
        }

        if (wid < 16) {
            const float* xs = UB + ng * 8;
            const float* mp = Mg + colb;
            #pragma unroll 2
            for (int k = 0; k < 194; k++)
                step2(acc, mp + k * 128, xs + k * XSTR);
        } else if (wid < 24) {
            const float* xs = UB + ng * 8;
            const float* mp = Mi + (colb - 128);
            #pragma unroll 2
            for (int k = 0; k < 130; k++) {
                int xk = (k < 128) ? k : (64 + k);   // 128->192, 129->193
                step2(acc, mp + k * 64, xs + xk * XSTR);
            }
        } else {
            const float* xs = UB + ng * 8 + 128 * XSTR;
            const float* mp = Mh + (colb - 192);
            #pragma unroll 2
            for (int k = 0; k < 64; k++)
                step2(acc, mp + k * 64, xs + k * XSTR);
        }
        __syncthreads();   // X no longer needed; UB becomes Epi

        // ---- write partials into Epi[64][256] ----
        #pragma unroll
        for (int p = 0; p < 4; p++) {
            #pragma unroll
            for (int c = 0; c < 2; c++) {
                float lo, hi;
                upk2(acc[p * 2 + c], lo, hi);
                UB[(ng * 8 + p * 2 + 0) * C_TOT + colb + c] = lo;
                UB[(ng * 8 + p * 2 + 1) * C_TOT + colb + c] = hi;
            }
        }
        __syncthreads();

        // ---- GRU: 64 nodes x 64 dims = 4096 outputs, 4 per thread ----
        #pragma unroll
        for (int j = 0; j < 4; j++) {
            int o = tid + j * NTHREADS;
            int i = o >> 6;
            int a = o & 63;
            int n = node0 + i;
            if (n < n_nodes) {
                float gr   = UB[i * C_TOT + a];
                float gi   = UB[i * C_TOT + 64 + a];
                float g_in = UB[i * C_TOT + 128 + a];
                float g_hn = UB[i * C_TOT + 192 + a];
                float r  = fsig(gr);
                float ig = fsig(gi);
                float newg = ftanh(g_in + r * g_hn);
                float h = hidden[(size_t)n * D + a];
                out[(size_t)n * D + a] = (1.f - ig) * h + ig * newg;
            }
        }
        __syncthreads();   // protect UB before next tile's X build
    }
}

// ---------------- launch ----------------
extern "C" void kernel_launch(void* const* d_in, const int* in_sizes, int n_in,
                              void* d_out, int out_size) {
    const float* hidden  = (const float*)d_in[0];
    const int*   in_src  = (const int*)  d_in[1];
    const int*   in_dst  = (const int*)  d_in[2];
    const float* in_w    = (const float*)d_in[3];
    const int*   out_src = (const int*)  d_in[4];
    const int*   out_dst = (const int*)  d_in[5];
    const float* out_w   = (const float*)d_in[6];
    const float* W_in    = (const float*)d_in[7];
    const float* b_in    = (const float*)d_in[8];
    const float* W_out   = (const float*)d_in[9];
    const float* b_out   = (const float*)d_in[10];
    const float* W_ih    = (const float*)d_in[11];
    const float* b_ih    = (const float*)d_in[12];
    const float* W_hh    = (const float*)d_in[13];
    const float* b_hh    = (const float*)d_in[14];
    float* out = (float*)d_out;

    int n = in_sizes[0] / D;
    if (n > MAXN) n = MAXN;
    int E = in_sizes[1];

    precompute_kernel<<<K_PAD, C_TOT>>>(W_in, b_in, W_out, b_out, W_ih, b_ih, W_hh, b_hh);
    zero_kernel<<<1184, 256>>>(n);
    if (E > 0) {
        dim3 grid(1184, 2);
        scatter_kernel<<<grid, 256>>>((const float4*)hidden,
                                      in_src, in_dst, in_w,
                                      out_src, out_dst, out_w, E, n);
    }

    int ntiles = (n + TILE_N - 1) / TILE_N;
    int grid_n = ntiles < GRID_SM ? ntiles : GRID_SM;
    size_t smem_bytes = (size_t)SMEM_FLOATS * sizeof(float);
    cudaFuncSetAttribute(node_kernel, cudaFuncAttributeMaxDynamicSharedMemorySize,
                         (int)smem_bytes);
    node_kernel<<<grid_n, NTHREADS, smem_bytes>>>(hidden, out, n, ntiles);
}

// round 10
// speedup vs baseline: 1.0377x; 1.0377x over previous
#include <cuda_runtime.h>
#include <cuda_bf16.h>
#include <math.h>
#include <stdint.h>

#define MAXN 100000
#define D 64
#define K_PAD 208
#define C_TOT 256      // cols: [0:64) r, [64:128) i, [128:192) i_n, [192:256) h_n
#define TILE_N 64      // nodes per tile
#define NTHREADS 1024
#define GRID_SM 148
#define XSTR 68        // Xs row stride in floats (64 nodes + 4 pad)

// smem partition (floats):
//  Mg [194][128] : 24832   gate cols 0-127, K rows 0-193
//  Mi [130][64]  : 8320    i_n cols 128-191, rows 0-127 then 192,193
//  Mh [64][64]   : 4096    h_n cols 192-255, rows 128-191
//  UB [16384]    : union — Xs[194][68] mainloop, Epi[64][256] epilogue
#define OFF_MG 0
#define OFF_MI 24832
#define OFF_MH 33152
#define OFF_UB 37248
#define SMEM_FLOATS 53632   // 214,528 bytes

// ---------------- scratch ----------------
__device__ float g_S[2 * (size_t)MAXN * D];
__device__ float g_s[2 * MAXN];
__device__ float g_M[K_PAD * C_TOT];
__device__ float g_bias[C_TOT];

// ---------------- kernel 1: precompute fused matrix ----------------
__global__ void precompute_kernel(const float* __restrict__ W_in, const float* __restrict__ b_in,
                                  const float* __restrict__ W_out, const float* __restrict__ b_out,
                                  const float* __restrict__ W_ih, const float* __restrict__ b_ih,
                                  const float* __restrict__ W_hh, const float* __restrict__ b_hh) {
    int k = blockIdx.x;
    int c = threadIdx.x;
    float v = 0.f;
    if (k < 64) {
        if (c < 192) {
            float a = 0.f;
            #pragma unroll 8
            for (int t = 0; t < 64; t++) a += W_in[k * 64 + t] * W_ih[t * 192 + c];
            v = a;
        }
    } else if (k < 128) {
        if (c < 192) {
            int aa = k - 64;
            float a = 0.f;
            #pragma unroll 8
            for (int t = 0; t < 64; t++) a += W_out[aa * 64 + t] * W_ih[(64 + t) * 192 + c];
            v = a;
        }
    } else if (k < 192) {
        int aa = k - 128;
        if (c < 128) v = W_hh[aa * 192 + c];
        else if (c >= 192) v = W_hh[aa * 192 + 128 + (c - 192)];
    } else if (k == 192) {
        if (c < 192) {
            float a = 0.f;
            for (int t = 0; t < 64; t++) a += b_in[t] * W_ih[t * 192 + c];
            v = a;
        }
    } else if (k == 193) {
        if (c < 192) {
            float a = 0.f;
            for (int t = 0; t < 64; t++) a += b_out[t] * W_ih[(64 + t) * 192 + c];
            v = a;
        }
    }
    g_M[k * C_TOT + c] = v;
    if (k == 0) {
        float b;
        if (c < 128)      b = b_ih[c] + b_hh[c];
        else if (c < 192) b = b_ih[c];
        else              b = b_hh[c - 64];
        g_bias[c] = b;
    }
}

// ---------------- kernel 2: zero accumulators ----------------
__global__ void zero_kernel(int n) {
    long totS = 2L * n * D;
    long tots = 2L * n;
    long tid = (long)blockIdx.x * blockDim.x + threadIdx.x;
    long stride = (long)gridDim.x * blockDim.x;
    float4 z = make_float4(0.f, 0.f, 0.f, 0.f);
    float4* S4 = reinterpret_cast<float4*>(g_S);
    for (long i = tid; i < totS / 4; i += stride) S4[i] = z;
    long rem = tots / 4;
    float4* s4 = reinterpret_cast<float4*>(g_s);
    for (long i = tid; i < rem; i += stride) s4[i] = z;
    for (long i = rem * 4 + tid; i < tots; i += stride) g_s[i] = 0.f;
}

// ---------------- kernel 3: edge scatter ----------------
__global__ void scatter_kernel(const float4* __restrict__ h4,
                               const int* __restrict__ srcA, const int* __restrict__ dstA,
                               const float* __restrict__ wA,
                               const int* __restrict__ srcB, const int* __restrict__ dstB,
                               const float* __restrict__ wB,
                               int E, int n) {
    int set = blockIdx.y;
    const int*   src = set ? srcB : srcA;
    const int*   dst = set ? dstB : dstA;
    const float* wp  = set ? wB   : wA;
    float* S  = g_S + (size_t)set * n * D;
    float* sw = g_s + (size_t)set * n;

    int lane = threadIdx.x & 31;
    int wid  = (blockIdx.x * blockDim.x + threadIdx.x) >> 5;
    int nw   = (gridDim.x * blockDim.x) >> 5;

    for (long base = (long)wid * 32; base < E; base += (long)nw * 32) {
        long e = base + lane;
        int s = 0, d = 0; float w = 0.f;
        if (e < E) { s = src[e]; d = dst[e]; w = wp[e]; }
        int cnt = (int)min((long)32, (long)E - base);
        for (int j = 0; j < cnt; j += 2) {
            int jj = j + (lane >> 4);
            float ww = __shfl_sync(0xffffffffu, w, jj);
            int   ss = __shfl_sync(0xffffffffu, s, jj);
            int   dd = __shfl_sync(0xffffffffu, d, jj);
            if (jj < cnt) {
                int l = lane & 15;
                float4 v = h4[(size_t)ss * 16 + l];
                float* p = S + (size_t)dd * D + l * 4;
                asm volatile("red.global.add.v4.f32 [%0], {%1,%2,%3,%4};"
                             :: "l"(p), "f"(v.x * ww), "f"(v.y * ww),
                                "f"(v.z * ww), "f"(v.w * ww) : "memory");
                if (l == 0)
                    asm volatile("red.global.add.f32 [%0], %1;"
                                 :: "l"(sw + dd), "f"(ww) : "memory");
            }
        }
    }
}

__device__ __forceinline__ float fsig(float x) { return 1.f / (1.f + __expf(-x)); }
__device__ __forceinline__ float ftanh(float x) { return 2.f / (1.f + __expf(-2.f * x)) - 1.f; }

// one k-step: 32 FFMA, 8 nodes x 4 cols
__device__ __forceinline__ void step84(float acc[8][4], const float* mp, const float* xp) {
    float4 m  = *reinterpret_cast<const float4*>(mp);
    float4 xa = *reinterpret_cast<const float4*>(xp);
    float4 xb = *reinterpret_cast<const float4*>(xp + 4);
    acc[0][0]+=xa.x*m.x; acc[0][1]+=xa.x*m.y; acc[0][2]+=xa.x*m.z; acc[0][3]+=xa.x*m.w;
    acc[1][0]+=xa.y*m.x; acc[1][1]+=xa.y*m.y; acc[1][2]+=xa.y*m.z; acc[1][3]+=xa.y*m.w;
    acc[2][0]+=xa.z*m.x; acc[2][1]+=xa.z*m.y; acc[2][2]+=xa.z*m.z; acc[2][3]+=xa.z*m.w;
    acc[3][0]+=xa.w*m.x; acc[3][1]+=xa.w*m.y; acc[3][2]+=xa.w*m.z; acc[3][3]+=xa.w*m.w;
    acc[4][0]+=xb.x*m.x; acc[4][1]+=xb.x*m.y; acc[4][2]+=xb.x*m.z; acc[4][3]+=xb.x*m.w;
    acc[5][0]+=xb.y*m.x; acc[5][1]+=xb.y*m.y; acc[5][2]+=xb.y*m.z; acc[5][3]+=xb.y*m.w;
    acc[6][0]+=xb.z*m.x; acc[6][1]+=xb.z*m.y; acc[6][2]+=xb.z*m.z; acc[6][3]+=xb.z*m.w;
    acc[7][0]+=xb.w*m.x; acc[7][1]+=xb.w*m.y; acc[7][2]+=xb.w*m.z; acc[7][3]+=xb.w*m.w;
}

// ---------------- kernel 4: persistent fused node GEMM + GRU ----------------
// 148 CTAs x 1024 threads. Thread tile: 8 nodes x 4 cols, K split in 2 halves.
// Warps 0-15:  gates (cols 0-127):  ng=w&7, kh=w>>3, colb=lane*4.       K-halves 97/97.
// Warps 16-23: i_n (cols 128-191):  kh=(w-16)>>2, ng=((w-16)&3)*2+(lane>>4),
//              colb=128+(lane&15)*4. Mi rows kh0: 0-64, kh1: 65-129 (X rows r<128?r:r+64).
// Warps 24-31: h_n (cols 192-255):  kh=(w-24)>>2, ng=((w-24)&3)*2+(lane>>4),
//              colb=192+(lane&15)*4. Mh rows kh0: 0-31, kh1: 32-63 (X rows 128+r).
// Per-SMSP k-steps: 4*97 + 2*65 + 2*32 = 582 (balanced).
extern __shared__ float smem[];

__global__ __launch_bounds__(NTHREADS, 1) void node_kernel(const float* __restrict__ hidden,
                                                           float* __restrict__ out,
                                                           int n_nodes, int ntiles) {
    float* Mg = smem + OFF_MG;
    float* Mi = smem + OFF_MI;
    float* Mh = smem + OFF_MH;
    float* UB = smem + OFF_UB;

    int tid = threadIdx.x;
    int wid = tid >> 5;
    int lane = tid & 31;

    // ---- load M panels once ----
    {
        float4* Mg4 = reinterpret_cast<float4*>(Mg);
        for (int i = tid; i < 194 * 32; i += NTHREADS) {
            int r = i >> 5, c4 = i & 31;
            Mg4[i] = *reinterpret_cast<const float4*>(&g_M[r * C_TOT + c4 * 4]);
        }
        float4* Mi4 = reinterpret_cast<float4*>(Mi);
        for (int i = tid; i < 130 * 16; i += NTHREADS) {
            int r = i >> 4, c4 = i & 15;
            int gr = (r < 128) ? r : (192 + (r - 128));
            Mi4[i] = *reinterpret_cast<const float4*>(&g_M[gr * C_TOT + 128 + c4 * 4]);
        }
        float4* Mh4 = reinterpret_cast<float4*>(Mh);
        for (int i = tid; i < 64 * 16; i += NTHREADS) {
            int r = i >> 4, c4 = i & 15;
            Mh4[i] = *reinterpret_cast<const float4*>(&g_M[(128 + r) * C_TOT + 192 + c4 * 4]);
        }
    }
    __syncthreads();

    const float* Sin  = g_S;
    const float* Sout = g_S + (size_t)n_nodes * D;

    // fixed thread -> (panel, kh, ng, colb)
    int kh, ng, colb;
    if (wid < 16)      { kh = wid >> 3;        ng = wid & 7;                        colb = lane * 4; }
    else if (wid < 24) { kh = (wid - 16) >> 2; ng = ((wid - 16) & 3) * 2 + (lane >> 4); colb = 128 + (lane & 15) * 4; }
    else               { kh = (wid - 24) >> 2; ng = ((wid - 24) & 3) * 2 + (lane >> 4); colb = 192 + (lane & 15) * 4; }

    for (int tile = blockIdx.x; tile < ntiles; tile += gridDim.x) {
        int node0 = tile * TILE_N;

        // ---- build X tile: Xs[k][node], 16 threads per node ----
        {
            int g = tid >> 4;
            int l = tid & 15;
            int n = node0 + g;
            bool nv = (n < n_nodes);
            #pragma unroll
            for (int k = l; k < 194; k += 16) {
                float v = 0.f;
                if (nv) {
                    if (k < 64)        v = Sin[(size_t)n * D + k];
                    else if (k < 128)  v = Sout[(size_t)n * D + (k - 64)];
                    else if (k < 192)  v = hidden[(size_t)n * D + (k - 128)];
                    else if (k == 192) v = g_s[n];
                    else               v = g_s[n_nodes + n];
                }
                UB[k * XSTR + g] = v;
            }
        }
        __syncthreads();

        // ---- GEMM: each warp-stream does its K-half, pointer-increment addressing ----
        float acc[8][4];
        if (kh == 0) {
            float4 bv = *reinterpret_cast<const float4*>(&g_bias[colb]);
            #pragma unroll
            for (int i = 0; i < 8; i++) { acc[i][0]=bv.x; acc[i][1]=bv.y; acc[i][2]=bv.z; acc[i][3]=bv.w; }
        } else {
            #pragma unroll
            for (int i = 0; i < 8; i++) { acc[i][0]=0.f; acc[i][1]=0.f; acc[i][2]=0.f; acc[i][3]=0.f; }
        }

        if (wid < 16) {
            // gates: K rows kh*97 .. kh*97+96
            const float* mp = Mg + (kh * 97) * 128 + colb;
            const float* xp = UB + (kh * 97) * XSTR + ng * 8;
            #pragma unroll 2
            for (int k = 0; k < 97; k++) {
                step84(acc, mp, xp);
                mp += 128; xp += XSTR;
            }
        } else if (wid < 24) {
            // i_n: Mi rows kh0: 0..64 (X rows same), kh1: 65..129 (X rows 65..127 then 192,193)
            if (kh == 0) {
                const float* mp = Mi + 0 * 64 + (colb - 128);
                const float* xp = UB + 0 * XSTR + ng * 8;
                #pragma unroll 2
                for (int k = 0; k < 65; k++) {
                    step84(acc, mp, xp);
                    mp += 64; xp += XSTR;
                }
            } else {
                const float* mp = Mi + 65 * 64 + (colb - 128);
                const float* xp = UB + 65 * XSTR + ng * 8;
                #pragma unroll 2
                for (int k = 0; k < 63; k++) {           // Mi rows 65..127
                    step84(acc, mp, xp);
                    mp += 64; xp += XSTR;
                }
                // Mi rows 128,129 -> X rows 192,193
                step84(acc, mp, UB + 192 * XSTR + ng * 8);
                step84(acc, mp + 64, UB + 193 * XSTR + ng * 8);
            }
        } else {
            // h_n: Mh rows kh*32 .. +31, X rows 128 + r
            const float* mp = Mh + (kh * 32) * 64 + (colb - 192);
            const float* xp = UB + (128 + kh * 32) * XSTR + ng * 8;
            #pragma unroll 2
            for (int k = 0; k < 32; k++) {
                step84(acc, mp, xp);
                mp += 64; xp += XSTR;
            }
        }
        __syncthreads();   // X no longer needed; UB becomes Epi

        // ---- combine K-halves through Epi[64][256] ----
        if (kh == 1) {
            #pragma unroll
            for (int i = 0; i < 8; i++)
                *reinterpret_cast<float4*>(&UB[(ng * 8 + i) * C_TOT + colb]) =
                    make_float4(acc[i][0], acc[i][1], acc[i][2], acc[i][3]);
        }
        __syncthreads();
        if (kh == 0) {
            #pragma unroll
            for (int i = 0; i < 8; i++) {
                float4* p = reinterpret_cast<float4*>(&UB[(ng * 8 + i) * C_TOT + colb]);
                float4 v = *p;
                v.x += acc[i][0]; v.y += acc[i][1]; v.z += acc[i][2]; v.w += acc[i][3];
                *p = v;
            }
        }
        __syncthreads();

        // ---- GRU: 64 nodes x 64 dims = 4096 outputs, 4 per thread ----
        #pragma unroll
        for (int j = 0; j < 4; j++) {
            int o = tid + j * NTHREADS;
            int i = o >> 6;
            int a = o & 63;
            int n = node0 + i;
            if (n < n_nodes) {
                float gr   = UB[i * C_TOT + a];
                float gi   = UB[i * C_TOT + 64 + a];
                float g_in = UB[i * C_TOT + 128 + a];
                float g_hn = UB[i * C_TOT + 192 + a];
                float r  = fsig(gr);
                float ig = fsig(gi);
                float newg = ftanh(g_in + r * g_hn);
                float h = hidden[(size_t)n * D + a];
                out[(size_t)n * D + a] = (1.f - ig) * h + ig * newg;
            }
        }
        __syncthreads();   // protect UB before next tile's X build
    }
}

// ---------------- launch ----------------
extern "C" void kernel_launch(void* const* d_in, const int* in_sizes, int n_in,
                              void* d_out, int out_size) {
    const float* hidden  = (const float*)d_in[0];
    const int*   in_src  = (const int*)  d_in[1];
    const int*   in_dst  = (const int*)  d_in[2];
    const float* in_w    = (const float*)d_in[3];
    const int*   out_src = (const int*)  d_in[4];
    const int*   out_dst = (const int*)  d_in[5];
    const float* out_w   = (const float*)d_in[6];
    const float* W_in    = (const float*)d_in[7];
    const float* b_in    = (const float*)d_in[8];
    const float* W_out   = (const float*)d_in[9];
    const float* b_out   = (const float*)d_in[10];
    const float* W_ih    = (const float*)d_in[11];
    const float* b_ih    = (const float*)d_in[12];
    const float* W_hh    = (const float*)d_in[13];
    const float* b_hh    = (const float*)d_in[14];
    float* out = (float*)d_out;

    int n = in_sizes[0] / D;
    if (n > MAXN) n = MAXN;
    int E = in_sizes[1];

    precompute_kernel<<<K_PAD, C_TOT>>>(W_in, b_in, W_out, b_out, W_ih, b_ih, W_hh, b_hh);
    zero_kernel<<<1184, 256>>>(n);
    if (E > 0) {
        dim3 grid(1184, 2);
        scatter_kernel<<<grid, 256>>>((const float4*)hidden,
                                      in_src, in_dst, in_w,
                                      out_src, out_dst, out_w, E, n);
    }

    int ntiles = (n + TILE_N - 1) / TILE_N;
    int grid_n = ntiles < GRID_SM ? ntiles : GRID_SM;
    size_t smem_bytes = (size_t)SMEM_FLOATS * sizeof(float);
    cudaFuncSetAttribute(node_kernel, cudaFuncAttributeMaxDynamicSharedMemorySize,
                         (int)smem_bytes);
    node_kernel<<<grid_n, NTHREADS, smem_bytes>>>(hidden, out, n, ntiles);
}

// round 11
// speedup vs baseline: 1.1424x; 1.1009x over previous
#include <cuda_runtime.h>
#include <cuda_bf16.h>
#include <math.h>
#include <stdint.h>

#define MAXN 100000
#define MAXE 1600000
#define D 64
#define K_PAD 208
#define C_TOT 256      // cols: [0:64) r, [64:128) i, [128:192) i_n, [192:256) h_n
#define TILE_N 64
#define NTHREADS 1024
#define GRID_SM 148
#define XSTR 68

// smem partition for node_kernel (floats)
#define OFF_MG 0
#define OFF_MI 24832
#define OFF_MH 33152
#define OFF_UB 37248
#define SMEM_FLOATS 53632   // 214,528 bytes

// ---------------- scratch ----------------
__device__ float g_S[2 * (size_t)MAXN * D];
__device__ float g_s[2 * MAXN];
__device__ float g_M[K_PAD * C_TOT];
__device__ float g_bias[C_TOT];
__device__ int   g_cnt[2 * MAXN];
__device__ int   g_off[2 * MAXN];       // after scan: exclusive offsets; after fill: segment ends
__device__ int   g_bsum[256];
__device__ int2  g_csr[2 * (size_t)MAXE];  // (src, w_bits)

// ---------------- kernel 1: precompute fused matrix ----------------
__global__ void precompute_kernel(const float* __restrict__ W_in, const float* __restrict__ b_in,
                                  const float* __restrict__ W_out, const float* __restrict__ b_out,
                                  const float* __restrict__ W_ih, const float* __restrict__ b_ih,
                                  const float* __restrict__ W_hh, const float* __restrict__ b_hh) {
    int k = blockIdx.x;
    int c = threadIdx.x;
    float v = 0.f;
    if (k < 64) {
        if (c < 192) {
            float a = 0.f;
            #pragma unroll 8
            for (int t = 0; t < 64; t++) a += W_in[k * 64 + t] * W_ih[t * 192 + c];
            v = a;
        }
    } else if (k < 128) {
        if (c < 192) {
            int aa = k - 64;
            float a = 0.f;
            #pragma unroll 8
            for (int t = 0; t < 64; t++) a += W_out[aa * 64 + t] * W_ih[(64 + t) * 192 + c];
            v = a;
        }
    } else if (k < 192) {
        int aa = k - 128;
        if (c < 128) v = W_hh[aa * 192 + c];
        else if (c >= 192) v = W_hh[aa * 192 + 128 + (c - 192)];
    } else if (k == 192) {
        if (c < 192) {
            float a = 0.f;
            for (int t = 0; t < 64; t++) a += b_in[t] * W_ih[t * 192 + c];
            v = a;
        }
    } else if (k == 193) {
        if (c < 192) {
            float a = 0.f;
            for (int t = 0; t < 64; t++) a += b_out[t] * W_ih[(64 + t) * 192 + c];
            v = a;
        }
    }
    g_M[k * C_TOT + c] = v;
    if (k == 0) {
        float b;
        if (c < 128)      b = b_ih[c] + b_hh[c];
        else if (c < 192) b = b_ih[c];
        else              b = b_hh[c - 64];
        g_bias[c] = b;
    }
}

// ---------------- CSR build ----------------
__global__ void zero_cnt_kernel(int nseg) {
    int i = blockIdx.x * blockDim.x + threadIdx.x;
    if (i < nseg) g_cnt[i] = 0;
}

__global__ void hist_kernel(const int* __restrict__ dstA, const int* __restrict__ dstB,
                            int E, int n) {
    int set = blockIdx.y;
    const int* dst = set ? dstB : dstA;
    int base = set * n;
    for (int e = blockIdx.x * blockDim.x + threadIdx.x; e < E; e += gridDim.x * blockDim.x)
        atomicAdd(&g_cnt[base + dst[e]], 1);
}

__global__ void scan1_kernel(int nseg) {
    __shared__ int sh[1024];
    int tid = threadIdx.x;
    int g = blockIdx.x * 1024 + tid;
    int x = (g < nseg) ? g_cnt[g] : 0;
    sh[tid] = x;
    __syncthreads();
    #pragma unroll
    for (int o = 1; o < 1024; o <<= 1) {
        int v = (tid >= o) ? sh[tid - o] : 0;
        __syncthreads();
        sh[tid] += v;
        __syncthreads();
    }
    if (g < nseg) g_off[g] = sh[tid] - x;     // exclusive
    if (tid == 1023) g_bsum[blockIdx.x] = sh[1023];
}

__global__ void scan2_kernel(int nblocks) {
    if (threadIdx.x == 0) {
        int run = 0;
        for (int i = 0; i < nblocks; i++) {
            int v = g_bsum[i];
            g_bsum[i] = run;
            run += v;
        }
    }
}

__global__ void scan3_kernel(int nseg) {
    int g = blockIdx.x * 1024 + threadIdx.x;
    if (g < nseg) g_off[g] += g_bsum[blockIdx.x];
}

__global__ void fill_kernel(const int* __restrict__ srcA, const int* __restrict__ dstA,
                            const float* __restrict__ wA,
                            const int* __restrict__ srcB, const int* __restrict__ dstB,
                            const float* __restrict__ wB,
                            int E, int n) {
    int set = blockIdx.y;
    const int*   src = set ? srcB : srcA;
    const int*   dst = set ? dstB : dstA;
    const float* wp  = set ? wB   : wA;
    int base = set * n;
    for (int e = blockIdx.x * blockDim.x + threadIdx.x; e < E; e += gridDim.x * blockDim.x) {
        int pos = atomicAdd(&g_off[base + dst[e]], 1);
        g_csr[pos] = make_int2(src[e], __float_as_int(wp[e]));
    }
}

// ---------------- gather: atomic-free segment sums ----------------
// Half-warp (16 lanes, float4 each) per segment; writes S and s directly.
__global__ void gather_kernel(const float4* __restrict__ h4, int nseg) {
    int l   = threadIdx.x & 15;                                   // lane within half-warp
    int hw  = (blockIdx.x * blockDim.x + threadIdx.x) >> 4;       // half-warp id
    int nhw = (gridDim.x * blockDim.x) >> 4;

    for (int s = hw; s < nseg; s += nhw) {
        int end = g_off[s];              // after fill: end of segment
        int cnt = g_cnt[s];
        int e = end - cnt;
        float4 acc = make_float4(0.f, 0.f, 0.f, 0.f);
        float ws = 0.f;
        #pragma unroll 2
        for (; e < end; e++) {
            int2 ed = g_csr[e];
            float w = __int_as_float(ed.y);
            float4 v = h4[(size_t)ed.x * 16 + l];
            acc.x += v.x * w; acc.y += v.y * w; acc.z += v.z * w; acc.w += v.w * w;
            ws += w;
        }
        reinterpret_cast<float4*>(g_S)[(size_t)s * 16 + l] = acc;
        if (l == 0) g_s[s] = ws;
    }
}

__device__ __forceinline__ float fsig(float x) { return 1.f / (1.f + __expf(-x)); }
__device__ __forceinline__ float ftanh(float x) { return 2.f / (1.f + __expf(-2.f * x)) - 1.f; }

// one k-step: 32 FFMA, 8 nodes x 4 cols
__device__ __forceinline__ void step84(float acc[8][4], const float* mp, const float* xp) {
    float4 m  = *reinterpret_cast<const float4*>(mp);
    float4 xa = *reinterpret_cast<const float4*>(xp);
    float4 xb = *reinterpret_cast<const float4*>(xp + 4);
    acc[0][0]+=xa.x*m.x; acc[0][1]+=xa.x*m.y; acc[0][2]+=xa.x*m.z; acc[0][3]+=xa.x*m.w;
    acc[1][0]+=xa.y*m.x; acc[1][1]+=xa.y*m.y; acc[1][2]+=xa.y*m.z; acc[1][3]+=xa.y*m.w;
    acc[2][0]+=xa.z*m.x; acc[2][1]+=xa.z*m.y; acc[2][2]+=xa.z*m.z; acc[2][3]+=xa.z*m.w;
    acc[3][0]+=xa.w*m.x; acc[3][1]+=xa.w*m.y; acc[3][2]+=xa.w*m.z; acc[3][3]+=xa.w*m.w;
    acc[4][0]+=xb.x*m.x; acc[4][1]+=xb.x*m.y; acc[4][2]+=xb.x*m.z; acc[4][3]+=xb.x*m.w;
    acc[5][0]+=xb.y*m.x; acc[5][1]+=xb.y*m.y; acc[5][2]+=xb.y*m.z; acc[5][3]+=xb.y*m.w;
    acc[6][0]+=xb.z*m.x; acc[6][1]+=xb.z*m.y; acc[6][2]+=xb.z*m.z; acc[6][3]+=xb.z*m.w;
    acc[7][0]+=xb.w*m.x; acc[7][1]+=xb.w*m.y; acc[7][2]+=xb.w*m.z; acc[7][3]+=xb.w*m.w;
}

// ---------------- node kernel (unchanged from R10) ----------------
extern __shared__ float smem[];

__global__ __launch_bounds__(NTHREADS, 1) void node_kernel(const float* __restrict__ hidden,
                                                           float* __restrict__ out,
                                                           int n_nodes, int ntiles) {
    float* Mg = smem + OFF_MG;
    float* Mi = smem + OFF_MI;
    float* Mh = smem + OFF_MH;
    float* UB = smem + OFF_UB;

    int tid = threadIdx.x;
    int wid = tid >> 5;
    int lane = tid & 31;

    {
        float4* Mg4 = reinterpret_cast<float4*>(Mg);
        for (int i = tid; i < 194 * 32; i += NTHREADS) {
            int r = i >> 5, c4 = i & 31;
            Mg4[i] = *reinterpret_cast<const float4*>(&g_M[r * C_TOT + c4 * 4]);
        }
        float4* Mi4 = reinterpret_cast<float4*>(Mi);
        for (int i = tid; i < 130 * 16; i += NTHREADS) {
            int r = i >> 4, c4 = i & 15;
            int gr = (r < 128) ? r : (192 + (r - 128));
            Mi4[i] = *reinterpret_cast<const float4*>(&g_M[gr * C_TOT + 128 + c4 * 4]);
        }
        float4* Mh4 = reinterpret_cast<float4*>(Mh);
        for (int i = tid; i < 64 * 16; i += NTHREADS) {
            int r = i >> 4, c4 = i & 15;
            Mh4[i] = *reinterpret_cast<const float4*>(&g_M[(128 + r) * C_TOT + 192 + c4 * 4]);
        }
    }
    __syncthreads();

    const float* Sin  = g_S;
    const float* Sout = g_S + (size_t)n_nodes * D;

    int kh, ng, colb;
    if (wid < 16)      { kh = wid >> 3;        ng = wid & 7;                        colb = lane * 4; }
    else if (wid < 24) { kh = (wid - 16) >> 2; ng = ((wid - 16) & 3) * 2 + (lane >> 4); colb = 128 + (lane & 15) * 4; }
    else               { kh = (wid - 24) >> 2; ng = ((wid - 24) & 3) * 2 + (lane >> 4); colb = 192 + (lane & 15) * 4; }

    for (int tile = blockIdx.x; tile < ntiles; tile += gridDim.x) {
        int node0 = tile * TILE_N;

        {
            int g = tid >> 4;
            int l = tid & 15;
            int n = node0 + g;
            bool nv = (n < n_nodes);
            #pragma unroll
            for (int k = l; k < 194; k += 16) {
                float v = 0.f;
                if (nv) {
                    if (k < 64)        v = Sin[(size_t)n * D + k];
                    else if (k < 128)  v = Sout[(size_t)n * D + (k - 64)];
                    else if (k < 192)  v = hidden[(size_t)n * D + (k - 128)];
                    else if (k == 192) v = g_s[n];
                    else               v = g_s[n_nodes + n];
                }
                UB[k * XSTR + g] = v;
            }
        }
        __syncthreads();

        float acc[8][4];
        if (kh == 0) {
            float4 bv = *reinterpret_cast<const float4*>(&g_bias[colb]);
            #pragma unroll
            for (int i = 0; i < 8; i++) { acc[i][0]=bv.x; acc[i][1]=bv.y; acc[i][2]=bv.z; acc[i][3]=bv.w; }
        } else {
            #pragma unroll
            for (int i = 0; i < 8; i++) { acc[i][0]=0.f; acc[i][1]=0.f; acc[i][2]=0.f; acc[i][3]=0.f; }
        }

        if (wid < 16) {
            const float* mp = Mg + (kh * 97) * 128 + colb;
            const float* xp = UB + (kh * 97) * XSTR + ng * 8;
            #pragma unroll 2
            for (int k = 0; k < 97; k++) {
                step84(acc, mp, xp);
                mp += 128; xp += XSTR;
            }
        } else if (wid < 24) {
            if (kh == 0) {
                const float* mp = Mi + (colb - 128);
                const float* xp = UB + ng * 8;
                #pragma unroll 2
                for (int k = 0; k < 65; k++) {
                    step84(acc, mp, xp);
                    mp += 64; xp += XSTR;
                }
            } else {
                const float* mp = Mi + 65 * 64 + (colb - 128);
                const float* xp = UB + 65 * XSTR + ng * 8;
                #pragma unroll 2
                for (int k = 0; k < 63; k++) {
                    step84(acc, mp, xp);
                    mp += 64; xp += XSTR;
                }
                step84(acc, mp, UB + 192 * XSTR + ng * 8);
                step84(acc, mp + 64, UB + 193 * XSTR + ng * 8);
            }
        } else {
            const float* mp = Mh + (kh * 32) * 64 + (colb - 192);
            const float* xp = UB + (128 + kh * 32) * XSTR + ng * 8;
            #pragma unroll 2
            for (int k = 0; k < 32; k++) {
                step84(acc, mp, xp);
                mp += 64; xp += XSTR;
            }
        }
        __syncthreads();

        if (kh == 1) {
            #pragma unroll
            for (int i = 0; i < 8; i++)
                *reinterpret_cast<float4*>(&UB[(ng * 8 + i) * C_TOT + colb]) =
                    make_float4(acc[i][0], acc[i][1], acc[i][2], acc[i][3]);
        }
        __syncthreads();
        if (kh == 0) {
            #pragma unroll
            for (int i = 0; i < 8; i++) {
                float4* p = reinterpret_cast<float4*>(&UB[(ng * 8 + i) * C_TOT + colb]);
                float4 v = *p;
                v.x += acc[i][0]; v.y += acc[i][1]; v.z += acc[i][2]; v.w += acc[i][3];
                *p = v;
            }
        }
        __syncthreads();

        #pragma unroll
        for (int j = 0; j < 4; j++) {
            int o = tid + j * NTHREADS;
            int i = o >> 6;
            int a = o & 63;
            int n = node0 + i;
            if (n < n_nodes) {
                float gr   = UB[i * C_TOT + a];
                float gi   = UB[i * C_TOT + 64 + a];
                float g_in = UB[i * C_TOT + 128 + a];
                float g_hn = UB[i * C_TOT + 192 + a];
                float r  = fsig(gr);
                float ig = fsig(gi);
                float newg = ftanh(g_in + r * g_hn);
                float h = hidden[(size_t)n * D + a];
                out[(size_t)n * D + a] = (1.f - ig) * h + ig * newg;
            }
        }
        __syncthreads();
    }
}

// ---------------- launch ----------------
extern "C" void kernel_launch(void* const* d_in, const int* in_sizes, int n_in,
                              void* d_out, int out_size) {
    const float* hidden  = (const float*)d_in[0];
    const int*   in_src  = (const int*)  d_in[1];
    const int*   in_dst  = (const int*)  d_in[2];
    const float* in_w    = (const float*)d_in[3];
    const int*   out_src = (const int*)  d_in[4];
    const int*   out_dst = (const int*)  d_in[5];
    const float* out_w   = (const float*)d_in[6];
    const float* W_in    = (const float*)d_in[7];
    const float* b_in    = (const float*)d_in[8];
    const float* W_out   = (const float*)d_in[9];
    const float* b_out   = (const float*)d_in[10];
    const float* W_ih    = (const float*)d_in[11];
    const float* b_ih    = (const float*)d_in[12];
    const float* W_hh    = (const float*)d_in[13];
    const float* b_hh    = (const float*)d_in[14];
    float* out = (float*)d_out;

    int n = in_sizes[0] / D;
    if (n > MAXN) n = MAXN;
    int E = in_sizes[1];
    if (E > MAXE) E = MAXE;

    int nseg = 2 * n;
    int sblk = (nseg + 1023) / 1024;     // <= 196

    precompute_kernel<<<K_PAD, C_TOT>>>(W_in, b_in, W_out, b_out, W_ih, b_ih, W_hh, b_hh);

    // CSR build
    zero_cnt_kernel<<<sblk, 1024>>>(nseg);
    if (E > 0) {
        dim3 hgrid(592, 2);
        hist_kernel<<<hgrid, 256>>>(in_dst, out_dst, E, n);
    }
    scan1_kernel<<<sblk, 1024>>>(nseg);
    scan2_kernel<<<1, 32>>>(sblk);
    scan3_kernel<<<sblk, 1024>>>(nseg);
    if (E > 0) {
        dim3 fgrid(592, 2);
        fill_kernel<<<fgrid, 256>>>(in_src, in_dst, in_w, out_src, out_dst, out_w, E, n);
    }

    // atomic-free gather
    gather_kernel<<<1184, 256>>>((const float4*)hidden, nseg);

    // fused node GEMM + GRU
    int ntiles = (n + TILE_N - 1) / TILE_N;
    int grid_n = ntiles < GRID_SM ? ntiles : GRID_SM;
    size_t smem_bytes = (size_t)SMEM_FLOATS * sizeof(float);
    cudaFuncSetAttribute(node_kernel, cudaFuncAttributeMaxDynamicSharedMemorySize,
                         (int)smem_bytes);
    node_kernel<<<grid_n, NTHREADS, smem_bytes>>>(hidden, out, n, ntiles);
}